// round 7
// baseline (speedup 1.0000x reference)
#include <cuda_runtime.h>
#include <cstdint>
#include <math.h>

// input_feats: [B=8, L=4096, C=2048] fp32   (H = W = 64)
// points_yx:   [B=8, M=4, P=512, 2] fp32
// output:      [B=8, M=4, O=64, C=2048] fp32
//
// out[b,m,o,c] = sum_{j=0..31} w_j * feat[b, idx_j, c]
//
// Round-7 (= R6 with compile fix): cp.async pipelined gather. In-flight
// gather data lives in a 6-stage SMEM ring instead of registers, decoupling
// MLP from register pressure: 48 warps/SM (occ 6) each with 6 outstanding
// 16B loads. Each thread reads only its own SMEM slot -> no __syncthreads
// in the main loop; cp.async.wait_group gives per-thread ordering.

#define H 64
#define W 64
#define C 2048
#define CV4 (C / 4)
#define M_MASKS 4
#define P_PTS 512
#define O_POOL 64
#define KCHUNK 8
#define NPAIR 32
#define STAGES 6

__device__ __forceinline__ void cp_async16(unsigned int smem_addr, const void* gptr) {
    asm volatile("cp.async.cg.shared.global [%0], [%1], 16;\n"
                 :: "r"(smem_addr), "l"(gptr) : "memory");
}
__device__ __forceinline__ void cp_commit() {
    asm volatile("cp.async.commit_group;\n" ::: "memory");
}
__device__ __forceinline__ void cp_wait5() {
    asm volatile("cp.async.wait_group %0;\n" :: "n"(STAGES - 1) : "memory");
}

__global__ __launch_bounds__(256, 6)
void point_sample_pool_kernel(const float* __restrict__ feats,
                              const float* __restrict__ pts,
                              float* __restrict__ out)
{
    // blockIdx.x in [0, 4096): bmo*2 + half (b-major ordering preserved)
    const int half = blockIdx.x & 1;
    const int bmo  = blockIdx.x >> 1;
    const int o    = bmo & (O_POOL - 1);
    const int bm   = bmo >> 6;               // b*4 + m
    const int b    = bm >> 2;

    __shared__ int    s_idx[NPAIR];
    __shared__ float  s_w[NPAIR];
    __shared__ float4 buf[STAGES][256];      // 24 KB ring

    const int tid = threadIdx.x;

    if (tid < NPAIR) {
        const int p_local = tid >> 2;
        const int corner  = tid & 3;
        const int p = o * KCHUNK + p_local;
        const float* pp = pts + ((size_t)bm * P_PTS + p) * 2;
        const float iy = pp[0] * (float)(H - 1);
        const float ix = pp[1] * (float)(W - 1);
        const float y0f = floorf(iy);
        const float x0f = floorf(ix);
        const float wy = iy - y0f;
        const float wx = ix - x0f;
        int y0 = (int)y0f; y0 = max(0, min(y0, H - 1));
        int x0 = (int)x0f; x0 = max(0, min(x0, W - 1));
        const int y1 = min(y0 + 1, H - 1);
        const int x1 = min(x0 + 1, W - 1);

        const int   yi  = (corner & 2) ? y1 : y0;
        const int   xi  = (corner & 1) ? x1 : x0;
        const float wyc = (corner & 2) ? wy : (1.0f - wy);
        const float wxc = (corner & 1) ? wx : (1.0f - wx);

        s_idx[tid] = yi * W + xi;
        s_w[tid]   = wyc * wxc * (1.0f / (float)KCHUNK);
    }
    __syncthreads();

    // This CTA owns float4 slots [half*256, half*256+256) of each row.
    const int c4 = half * 256 + tid;
    const float4* base = (const float4*)(feats + (size_t)b * (H * W) * C) + c4;

    // Per-thread SMEM slot addresses for each stage.
    const unsigned int my_slot =
        (unsigned int)__cvta_generic_to_shared(&buf[0][tid]);
    const unsigned int stage_stride = 256 * sizeof(float4);   // 4096 B

    // Prefetch STAGES rows (one group per stage).
    #pragma unroll
    for (int s = 0; s < STAGES; s++) {
        cp_async16(my_slot + s * stage_stride, base + (size_t)s_idx[s] * CV4);
        cp_commit();
    }

    float4 acc0 = make_float4(0.f, 0.f, 0.f, 0.f);
    float4 acc1 = make_float4(0.f, 0.f, 0.f, 0.f);

    #pragma unroll
    for (int j = 0; j < NPAIR; j++) {
        cp_wait5();                           // stage (j % STAGES) ready
        const int st = j % STAGES;
        const float4 v = buf[st][tid];
        // Refill this stage (or empty commit to keep group count uniform).
        if (j + STAGES < NPAIR) {
            cp_async16(my_slot + st * stage_stride,
                       base + (size_t)s_idx[j + STAGES] * CV4);
        }
        cp_commit();
        const float w = s_w[j];
        float4& a = (j & 1) ? acc1 : acc0;
        a.x = fmaf(w, v.x, a.x);
        a.y = fmaf(w, v.y, a.y);
        a.z = fmaf(w, v.z, a.z);
        a.w = fmaf(w, v.w, a.w);
    }

    acc0.x += acc1.x; acc0.y += acc1.y; acc0.z += acc1.z; acc0.w += acc1.w;

    float4* op = (float4*)(out + (size_t)bmo * C) + c4;
    __stcs(op, acc0);
}

extern "C" void kernel_launch(void* const* d_in, const int* in_sizes, int n_in,
                              void* d_out, int out_size)
{
    const float* feats = (const float*)d_in[0];
    const float* pts   = (const float*)d_in[1];
    float* out = (float*)d_out;

    const int grid = 8 * M_MASKS * O_POOL * 2;   // 4096 CTAs
    point_sample_pool_kernel<<<grid, 256>>>(feats, pts, out);
}

// round 8
// speedup vs baseline: 1.0648x; 1.0648x over previous
#include <cuda_runtime.h>
#include <math.h>

// input_feats: [B=8, L=4096, C=2048] fp32   (H = W = 64)
// points_yx:   [B=8, M=4, P=512, 2] fp32
// output:      [B=8, M=4, O=64, C=2048] fp32
//
// out[b,m,o,c] = sum_{j=0..31} w_j * feat[b, idx_j, c]
//
// Round-8: R3 base (grid 4096 half-rows, register gather, streaming store)
// with occupancy 6 (40-reg budget -> 48 warps/SM) and UF=6 front-batched
// loads. The kernel is pinned at ~97% of the LTS read cap (512 MB through
// L2); this probes whether more per-SM request streams squeeze the last few
// percent of L2 efficiency.

#define H 64
#define W 64
#define C 2048
#define CV4 (C / 4)
#define M_MASKS 4
#define P_PTS 512
#define O_POOL 64
#define KCHUNK 8
#define NPAIR 32
#define UF 6                 // 6 front-batched float4 loads (24 data regs)

__global__ __launch_bounds__(256, 6)
void point_sample_pool_kernel(const float* __restrict__ feats,
                              const float* __restrict__ pts,
                              float* __restrict__ out)
{
    // blockIdx.x in [0, 4096): bmo*2 + half (b-major ordering preserved)
    const int half = blockIdx.x & 1;
    const int bmo  = blockIdx.x >> 1;
    const int o    = bmo & (O_POOL - 1);
    const int bm   = bmo >> 6;               // b*4 + m
    const int b    = bm >> 2;

    __shared__ int   s_idx[NPAIR];
    __shared__ float s_w[NPAIR];

    const int tid = threadIdx.x;

    if (tid < NPAIR) {
        const int p_local = tid >> 2;
        const int corner  = tid & 3;
        const int p = o * KCHUNK + p_local;
        const float* pp = pts + ((size_t)bm * P_PTS + p) * 2;
        const float iy = pp[0] * (float)(H - 1);
        const float ix = pp[1] * (float)(W - 1);
        const float y0f = floorf(iy);
        const float x0f = floorf(ix);
        const float wy = iy - y0f;
        const float wx = ix - x0f;
        int y0 = (int)y0f; y0 = max(0, min(y0, H - 1));
        int x0 = (int)x0f; x0 = max(0, min(x0, W - 1));
        const int y1 = min(y0 + 1, H - 1);
        const int x1 = min(x0 + 1, W - 1);

        const int   yi  = (corner & 2) ? y1 : y0;
        const int   xi  = (corner & 1) ? x1 : x0;
        const float wyc = (corner & 2) ? wy : (1.0f - wy);
        const float wxc = (corner & 1) ? wx : (1.0f - wx);

        s_idx[tid] = yi * W + xi;
        s_w[tid]   = wyc * wxc * (1.0f / (float)KCHUNK);
    }
    __syncthreads();

    const float4* base = (const float4*)(feats + (size_t)b * (H * W) * C);

    // This CTA owns float4 slots [half*256, half*256+256)
    const int c4 = half * 256 + tid;

    float4 acc0 = make_float4(0.f, 0.f, 0.f, 0.f);
    float4 acc1 = make_float4(0.f, 0.f, 0.f, 0.f);

    // 32 = 5*6 + 2: five UF=6 batches plus a 2-tail.
    #pragma unroll
    for (int j0 = 0; j0 < 30; j0 += UF) {
        float4 v[UF];
        #pragma unroll
        for (int u = 0; u < UF; u++) {
            v[u] = __ldg(base + (size_t)s_idx[j0 + u] * CV4 + c4);
        }
        #pragma unroll
        for (int u = 0; u < UF; u++) {
            const float w = s_w[j0 + u];
            float4& a = (u & 1) ? acc1 : acc0;
            a.x = fmaf(w, v[u].x, a.x);
            a.y = fmaf(w, v[u].y, a.y);
            a.z = fmaf(w, v[u].z, a.z);
            a.w = fmaf(w, v[u].w, a.w);
        }
    }
    {   // tail: j = 30, 31
        float4 v0 = __ldg(base + (size_t)s_idx[30] * CV4 + c4);
        float4 v1 = __ldg(base + (size_t)s_idx[31] * CV4 + c4);
        const float w0 = s_w[30];
        const float w1 = s_w[31];
        acc0.x = fmaf(w0, v0.x, acc0.x);
        acc0.y = fmaf(w0, v0.y, acc0.y);
        acc0.z = fmaf(w0, v0.z, acc0.z);
        acc0.w = fmaf(w0, v0.w, acc0.w);
        acc1.x = fmaf(w1, v1.x, acc1.x);
        acc1.y = fmaf(w1, v1.y, acc1.y);
        acc1.z = fmaf(w1, v1.z, acc1.z);
        acc1.w = fmaf(w1, v1.w, acc1.w);
    }

    acc0.x += acc1.x; acc0.y += acc1.y; acc0.z += acc1.z; acc0.w += acc1.w;

    float4* op = (float4*)(out + (size_t)bmo * C) + c4;
    __stcs(op, acc0);
}

extern "C" void kernel_launch(void* const* d_in, const int* in_sizes, int n_in,
                              void* d_out, int out_size)
{
    const float* feats = (const float*)d_in[0];
    const float* pts   = (const float*)d_in[1];
    float* out = (float*)d_out;

    const int grid = 8 * M_MASKS * O_POOL * 2;   // 4096 CTAs
    point_sample_pool_kernel<<<grid, 256>>>(feats, pts, out);
}

// round 9
// speedup vs baseline: 1.0655x; 1.0007x over previous
#include <cuda_runtime.h>
#include <math.h>

// input_feats: [B=8, L=4096, C=2048] fp32   (H = W = 64)
// points_yx:   [B=8, M=4, P=512, 2] fp32
// output:      [B=8, M=4, O=64, C=2048] fp32
//
// out[b,m,o,c] = sum_{j=0..31} w_j * feat[b, idx_j, c]
//
// Round-9: R3 base (grid 4096 half-rows, UF=8 register gather, occ 4,
// streaming store) with the SMEM+barrier setup replaced by per-warp
// redundant pair computation + shfl broadcast. Each warp computes all 32
// (idx, w) pairs in its own lanes and broadcasts them via __shfl_sync at
// use time -> no __syncthreads, warps start gathering independently.
// Kernel is at the LTS read cap (512 MB / 43.8us = ~6150 B/cyc); this
// only trims CTA-start latency.

#define H 64
#define W 64
#define C 2048
#define CV4 (C / 4)
#define M_MASKS 4
#define P_PTS 512
#define O_POOL 64
#define KCHUNK 8
#define NPAIR 32
#define UF 8

__global__ __launch_bounds__(256, 4)
void point_sample_pool_kernel(const float* __restrict__ feats,
                              const float* __restrict__ pts,
                              float* __restrict__ out)
{
    // blockIdx.x in [0, 4096): bmo*2 + half (b-major ordering preserved)
    const int half = blockIdx.x & 1;
    const int bmo  = blockIdx.x >> 1;
    const int o    = bmo & (O_POOL - 1);
    const int bm   = bmo >> 6;               // b*4 + m
    const int b    = bm >> 2;

    const int tid  = threadIdx.x;
    const int lane = tid & 31;

    // Every warp computes all 32 (idx, weight) pairs: lane = pair index.
    int   my_idx;
    float my_w;
    {
        const int p_local = lane >> 2;
        const int corner  = lane & 3;
        const int p = o * KCHUNK + p_local;
        const float* pp = pts + ((size_t)bm * P_PTS + p) * 2;
        const float iy = pp[0] * (float)(H - 1);
        const float ix = pp[1] * (float)(W - 1);
        const float y0f = floorf(iy);
        const float x0f = floorf(ix);
        const float wy = iy - y0f;
        const float wx = ix - x0f;
        int y0 = (int)y0f; y0 = max(0, min(y0, H - 1));
        int x0 = (int)x0f; x0 = max(0, min(x0, W - 1));
        const int y1 = min(y0 + 1, H - 1);
        const int x1 = min(x0 + 1, W - 1);

        const int   yi  = (corner & 2) ? y1 : y0;
        const int   xi  = (corner & 1) ? x1 : x0;
        const float wyc = (corner & 2) ? wy : (1.0f - wy);
        const float wxc = (corner & 1) ? wx : (1.0f - wx);

        my_idx = yi * W + xi;
        my_w   = wyc * wxc * (1.0f / (float)KCHUNK);
    }

    const float4* base = (const float4*)(feats + (size_t)b * (H * W) * C);

    // This CTA owns float4 slots [half*256, half*256+256)
    const int c4 = half * 256 + tid;

    float4 acc0 = make_float4(0.f, 0.f, 0.f, 0.f);
    float4 acc1 = make_float4(0.f, 0.f, 0.f, 0.f);

    #pragma unroll
    for (int j0 = 0; j0 < NPAIR; j0 += UF) {
        float4 v[UF];
        // Front-batch UF independent loads; indices via warp broadcast.
        #pragma unroll
        for (int u = 0; u < UF; u++) {
            const int idx = __shfl_sync(0xffffffffu, my_idx, j0 + u);
            v[u] = __ldg(base + (size_t)idx * CV4 + c4);
        }
        #pragma unroll
        for (int u = 0; u < UF; u++) {
            const float w = __shfl_sync(0xffffffffu, my_w, j0 + u);
            float4& a = (u & 1) ? acc1 : acc0;
            a.x = fmaf(w, v[u].x, a.x);
            a.y = fmaf(w, v[u].y, a.y);
            a.z = fmaf(w, v[u].z, a.z);
            a.w = fmaf(w, v[u].w, a.w);
        }
    }

    acc0.x += acc1.x; acc0.y += acc1.y; acc0.z += acc1.z; acc0.w += acc1.w;

    // Streaming store: output is never re-read.
    float4* op = (float4*)(out + (size_t)bmo * C) + c4;
    __stcs(op, acc0);
}

extern "C" void kernel_launch(void* const* d_in, const int* in_sizes, int n_in,
                              void* d_out, int out_size)
{
    const float* feats = (const float*)d_in[0];
    const float* pts   = (const float*)d_in[1];
    float* out = (float*)d_out;

    const int grid = 8 * M_MASKS * O_POOL * 2;   // 4096 CTAs
    point_sample_pool_kernel<<<grid, 256>>>(feats, pts, out);
}

// round 10
// speedup vs baseline: 1.1089x; 1.0408x over previous
#include <cuda_runtime.h>
#include <math.h>

// input_feats: [B=8, L=4096, C=2048] fp32   (H = W = 64)
// points_yx:   [B=8, M=4, P=512, 2] fp32
// output:      [B=8, M=4, O=64, C=2048] fp32
//
// out[b,m,o,c] = sum_{j=0..31} w_j * feat[b, idx_j, c]
// (32 pairs = 8 points x 4 bilinear corners, weights pre-divided by 8)
//
// FINAL (R3 config): this kernel runs at the LTS read-path ceiling:
// 512 MB of gather reads through L2 (65536 contributions x 8 KB,
// structurally irreducible) at ~11.7 TB/s ~= the measured ~6300 B/cyc
// path-independent L2 cap. DRAM bytes sit at the unique-footprint floor
// (~245 MB). Verified insensitive to occupancy (44-88%), MLP (2-8),
// request ordering (sorted/unsorted), and load path (LDG/LDGSTS).
//
// Config: grid 4096 = 2 CTAs per output row (channel halves; keeps the
// concurrent-CTA L2 window at ~1.2 batches so DRAM stays at the floor),
// occ 4 (64-reg budget), UF=8 front-batched float4 loads, SMEM-staged
// (idx, weight) pairs, streaming stores for the never-re-read output.

#define H 64
#define W 64
#define C 2048
#define CV4 (C / 4)
#define M_MASKS 4
#define P_PTS 512
#define O_POOL 64
#define KCHUNK 8
#define NPAIR 32
#define UF 8

__global__ __launch_bounds__(256, 4)
void point_sample_pool_kernel(const float* __restrict__ feats,
                              const float* __restrict__ pts,
                              float* __restrict__ out)
{
    // blockIdx.x in [0, 4096): bmo*2 + half (b-major ordering preserved)
    const int half = blockIdx.x & 1;
    const int bmo  = blockIdx.x >> 1;
    const int o    = bmo & (O_POOL - 1);
    const int bm   = bmo >> 6;               // b*4 + m
    const int b    = bm >> 2;

    __shared__ int   s_idx[NPAIR];
    __shared__ float s_w[NPAIR];

    const int tid = threadIdx.x;

    if (tid < NPAIR) {
        const int p_local = tid >> 2;
        const int corner  = tid & 3;
        const int p = o * KCHUNK + p_local;
        const float* pp = pts + ((size_t)bm * P_PTS + p) * 2;
        const float iy = pp[0] * (float)(H - 1);
        const float ix = pp[1] * (float)(W - 1);
        const float y0f = floorf(iy);
        const float x0f = floorf(ix);
        const float wy = iy - y0f;
        const float wx = ix - x0f;
        int y0 = (int)y0f; y0 = max(0, min(y0, H - 1));
        int x0 = (int)x0f; x0 = max(0, min(x0, W - 1));
        const int y1 = min(y0 + 1, H - 1);
        const int x1 = min(x0 + 1, W - 1);

        const int   yi  = (corner & 2) ? y1 : y0;
        const int   xi  = (corner & 1) ? x1 : x0;
        const float wyc = (corner & 2) ? wy : (1.0f - wy);
        const float wxc = (corner & 1) ? wx : (1.0f - wx);

        s_idx[tid] = yi * W + xi;
        s_w[tid]   = wyc * wxc * (1.0f / (float)KCHUNK);
    }
    __syncthreads();

    const float4* base = (const float4*)(feats + (size_t)b * (H * W) * C);

    // This CTA owns float4 slots [half*256, half*256+256)
    const int c4 = half * 256 + tid;

    float4 acc0 = make_float4(0.f, 0.f, 0.f, 0.f);
    float4 acc1 = make_float4(0.f, 0.f, 0.f, 0.f);

    #pragma unroll
    for (int j0 = 0; j0 < NPAIR; j0 += UF) {
        float4 v[UF];
        // Front-batch UF independent loads (MLP_p1 = UF)
        #pragma unroll
        for (int u = 0; u < UF; u++) {
            v[u] = __ldg(base + (size_t)s_idx[j0 + u] * CV4 + c4);
        }
        // Then consume
        #pragma unroll
        for (int u = 0; u < UF; u++) {
            const float w = s_w[j0 + u];
            float4& a = (u & 1) ? acc1 : acc0;
            a.x = fmaf(w, v[u].x, a.x);
            a.y = fmaf(w, v[u].y, a.y);
            a.z = fmaf(w, v[u].z, a.z);
            a.w = fmaf(w, v[u].w, a.w);
        }
    }

    acc0.x += acc1.x; acc0.y += acc1.y; acc0.z += acc1.z; acc0.w += acc1.w;

    // Streaming store: output is never re-read.
    float4* op = (float4*)(out + (size_t)bmo * C) + c4;
    __stcs(op, acc0);
}

extern "C" void kernel_launch(void* const* d_in, const int* in_sizes, int n_in,
                              void* d_out, int out_size)
{
    const float* feats = (const float*)d_in[0];
    const float* pts   = (const float*)d_in[1];
    float* out = (float*)d_out;

    const int grid = 8 * M_MASKS * O_POOL * 2;   // 4096 CTAs
    point_sample_pool_kernel<<<grid, 256>>>(feats, pts, out);
}